// round 6
// baseline (speedup 1.0000x reference)
#include <cuda_runtime.h>

#define BS   16
#define DD   4096
#define NN   512
#define RR   16
#define EPSV 1e-6f
#define INVT 100.0f

#define GRID   592          // 148 SMs * 4 blocks (all co-resident)
#define TPB    128
#define NSLICE 16           // P partial slices (256 d each)
#define NBTB   32           // BtB partial slices (128 d each)
#define NCTC   4

#define NU_PMAT 1024        // (b16, ds16, nc4)
#define NU_COEF 64          // (b16, nc4)
#define NU_QMAT 512         // (b16, dc32)
#define NU_OUT  512

typedef unsigned long long u64;

// ---------------- scratch ----------------
__device__ float g_bases[BS * DD * RR];
__device__ float g_coef [BS * NN * RR];
__device__ float g_Ppart[BS * NSLICE * NN * RR];   // 8 MB
__device__ float g_btbp [BS * NBTB * 256];
__device__ float g_ctcp [BS * NCTC * 256];

// barrier / work-stealing state
__device__ unsigned g_gen    = 0;
__device__ unsigned g_arrive = 0;
__device__ unsigned g_work   = 0;

// ---------------- packed f32x2 ----------------
__device__ __forceinline__ void ffma2(u64& acc, u64 a, u64 b) {
    asm("fma.rn.f32x2 %0, %1, %2, %3;" : "=l"(acc) : "l"(a), "l"(b), "l"(acc));
}
__device__ __forceinline__ u64 packf2(float lo, float hi) {
    u64 r; asm("mov.b64 %0, {%1, %2};" : "=l"(r) : "f"(lo), "f"(hi)); return r;
}
__device__ __forceinline__ void unpackf2(u64 v, float& lo, float& hi) {
    asm("mov.b64 {%0, %1}, %2;" : "=f"(lo), "=f"(hi) : "l"(v));
}
__device__ __forceinline__ void fma16_2(u64* acc2, u64 xv2, const float* __restrict__ row) {
    const ulonglong2* r2 = reinterpret_cast<const ulonglong2*>(row);
#pragma unroll
    for (int q = 0; q < 4; ++q) {
        ulonglong2 p = r2[q];
        ffma2(acc2[2*q+0], xv2, p.x);
        ffma2(acc2[2*q+1], xv2, p.y);
    }
}
__device__ __forceinline__ void unpack_acc(const u64* acc2, float* v) {
#pragma unroll
    for (int q = 0; q < 8; ++q) unpackf2(acc2[q], v[2*q], v[2*q+1]);
}

// ---------------- helpers ----------------
__device__ __forceinline__ void load16(const float* __restrict__ src, float* v) {
    const float4* s4 = reinterpret_cast<const float4*>(src);
#pragma unroll
    for (int q = 0; q < 4; ++q) {
        float4 t = s4[q];
        v[4*q+0] = t.x; v[4*q+1] = t.y; v[4*q+2] = t.z; v[4*q+3] = t.w;
    }
}
__device__ __forceinline__ void store16(float* __restrict__ dst, const float* v) {
    float4* d4 = reinterpret_cast<float4*>(dst);
#pragma unroll
    for (int q = 0; q < 4; ++q)
        d4[q] = make_float4(v[4*q+0], v[4*q+1], v[4*q+2], v[4*q+3]);
}
__device__ __forceinline__ void mat16(float* den, const float* v, const float* __restrict__ G) {
#pragma unroll
    for (int s2 = 0; s2 < 16; ++s2) den[s2] = 0.f;
#pragma unroll
    for (int r = 0; r < 16; ++r) {
        float c = v[r];
        const float* row = &G[r * 16];
#pragma unroll
        for (int s2 = 0; s2 < 16; ++s2) den[s2] = fmaf(c, row[s2], den[s2]);
    }
}

// ---------------- grid barrier (release/acquire, resets work counter) ----------------
__device__ __forceinline__ unsigned grid_barrier(unsigned gen) {
    __threadfence();
    __syncthreads();
    if (threadIdx.x == 0) {
        unsigned a = atomicAdd(&g_arrive, 1u);
        if (a == GRID - 1u) {
            g_arrive = 0u;
            atomicExch(&g_work, 0u);
            __threadfence();
            atomicAdd(&g_gen, 1u);          // release
        } else {
            while (*((volatile unsigned*)&g_gen) == gen) { /* spin */ }
        }
    }
    __syncthreads();
    __threadfence();                        // acquire
    return gen + 1u;
}

// ---------------- work stealing ----------------
__shared__ int sm_w;
__device__ __forceinline__ int grab() {
    __syncthreads();
    if (threadIdx.x == 0) sm_w = (int)atomicAdd(&g_work, 1u);
    __syncthreads();
    return sm_w;
}

// shared union: max(pmat 8320, qmat 8448, coef 2432) floats — MUST be 16B aligned
__shared__ __align__(16) float smu[8448];

// ---------------- pmat phase: P partials (+ optional BtB gram of source bases) ----------------
__device__ void pmat_phase(const float* __restrict__ x, const float* __restrict__ bsrc, bool gram) {
    const int tid = threadIdx.x;
    float* bss = smu;                                  // 4096 floats (256 d x 16 r)
    float (*xs)[33] = reinterpret_cast<float (*)[33]>(smu + 4096);

    for (;;) {
        int u = grab();
        if (u >= NU_PMAT) break;
        const int nc = u & 3;
        const int ds = (u >> 2) & 15;
        const int b  = u >> 6;

        {
            const float4* s = reinterpret_cast<const float4*>(
                bsrc + ((size_t)b * DD + (size_t)ds * 256) * RR);
            float4* d4 = reinterpret_cast<float4*>(bss);
#pragma unroll
            for (int i = 0; i < 8; ++i) d4[tid + i * 128] = s[tid + i * 128];
        }

        const float* xbase = x + ((size_t)b * NN + (size_t)nc * 128) * DD + (size_t)ds * 256;
        const int srow = tid >> 3;
        const int sc4  = tid & 7;

        u64 acc2[8];
#pragma unroll
        for (int q = 0; q < 8; ++q) acc2[q] = 0ull;

        float4 pre[8];
#pragma unroll
        for (int k = 0; k < 8; ++k)
            pre[k] = *reinterpret_cast<const float4*>(xbase + (size_t)(srow + k * 16) * DD + sc4 * 4);

        __syncthreads();   // bss ready

#pragma unroll 1
        for (int t0 = 0; t0 < 256; t0 += 32) {
#pragma unroll
            for (int k = 0; k < 8; ++k) {
                float* dp = &xs[srow + k * 16][sc4 * 4];
                dp[0] = pre[k].x; dp[1] = pre[k].y; dp[2] = pre[k].z; dp[3] = pre[k].w;
            }
            __syncthreads();
            if (t0 + 32 < 256) {
#pragma unroll
                for (int k = 0; k < 8; ++k)
                    pre[k] = *reinterpret_cast<const float4*>(
                        xbase + (size_t)(srow + k * 16) * DD + (t0 + 32) + sc4 * 4);
            }
#pragma unroll
            for (int j = 0; j < 32; ++j) {
                float xv = xs[tid][j];
                fma16_2(acc2, packf2(xv, xv), &bss[(t0 + j) * RR]);
            }
            __syncthreads();
        }

        float acc[16];
        unpack_acc(acc2, acc);
        const int n = nc * 128 + tid;
        store16(g_Ppart + (((size_t)b * NSLICE + ds) * NN + n) * RR, acc);

        if (gram && nc == 0) {
#pragma unroll
            for (int half = 0; half < 2; ++half) {
#pragma unroll
                for (int k = 0; k < 2; ++k) {
                    int p2 = tid + k * 128;
                    int r = p2 >> 4, s2 = p2 & 15;
                    float s = 0.f;
                    const float* base = &bss[half * 128 * 16];
#pragma unroll 8
                    for (int i = 0; i < 128; ++i)
                        s = fmaf(base[i * 16 + r], base[i * 16 + s2], s);
                    g_btbp[((size_t)b * NBTB + ds * 2 + half) * 256 + p2] = s;
                }
            }
        }
        __syncthreads();
    }
}

// ---------------- coef phase ----------------
__device__ void coef_phase(bool init) {
    const int tid = threadIdx.x;
    float* btbs = smu;                                   // 256
    float (*smcf)[17] = reinterpret_cast<float (*)[17]>(smu + 256);

    for (;;) {
        int u = grab();
        if (u >= NU_COEF) break;
        const int nc = u & 3;
        const int b  = u >> 2;

        if (tid < 64) {
            float4 s = make_float4(0.f, 0.f, 0.f, 0.f);
#pragma unroll
            for (int sl = 0; sl < NBTB; ++sl) {
                float4 v = *reinterpret_cast<const float4*>(
                    g_btbp + ((size_t)b * NBTB + sl) * 256 + tid * 4);
                s.x += v.x; s.y += v.y; s.z += v.z; s.w += v.w;
            }
            *reinterpret_cast<float4*>(&btbs[tid * 4]) = s;
        }

        const int n = nc * 128 + tid;
        float p[16];
#pragma unroll
        for (int r = 0; r < 16; ++r) p[r] = 0.f;
#pragma unroll
        for (int sl = 0; sl < NSLICE; ++sl) {
            const float4* pp = reinterpret_cast<const float4*>(
                g_Ppart + (((size_t)b * NSLICE + sl) * NN + n) * RR);
#pragma unroll
            for (int q = 0; q < 4; ++q) {
                float4 v = pp[q];
                p[4*q+0] += v.x; p[4*q+1] += v.y; p[4*q+2] += v.z; p[4*q+3] += v.w;
            }
        }

        float cf[16];
        if (init) {
            float m = p[0];
#pragma unroll
            for (int r = 1; r < 16; ++r) m = fmaxf(m, p[r]);
            float s = 0.f;
#pragma unroll
            for (int r = 0; r < 16; ++r) { cf[r] = __expf(INVT * (p[r] - m)); s += cf[r]; }
            float inv = 1.f / s;
#pragma unroll
            for (int r = 0; r < 16; ++r) cf[r] *= inv;
        } else {
            load16(g_coef + ((size_t)b * NN + n) * RR, cf);
        }
        __syncthreads();   // btbs ready

        float den[16];
        mat16(den, cf, btbs);
#pragma unroll
        for (int r = 0; r < 16; ++r) cf[r] = cf[r] * p[r] / (den[r] + EPSV);
        store16(g_coef + ((size_t)b * NN + n) * RR, cf);

#pragma unroll
        for (int r = 0; r < 16; ++r) smcf[tid][r] = cf[r];
        __syncthreads();
#pragma unroll
        for (int k = 0; k < 2; ++k) {
            int p2 = tid + k * 128;
            int r = p2 >> 4, s2 = p2 & 15;
            float s = 0.f;
#pragma unroll 8
            for (int i = 0; i < 128; ++i) s = fmaf(smcf[i][r], smcf[i][s2], s);
            g_ctcp[((size_t)b * NCTC + nc) * 256 + p2] = s;
        }
        __syncthreads();
    }
}

// ---------------- qmat phase: Q + bases update + BtB gram of new bases ----------------
__device__ void qmat_phase(const float* __restrict__ x, const float* __restrict__ bold) {
    const int tid = threadIdx.x;
    float* cfs  = smu;                                   // 8192
    float* ctcs = smu + 8192;                            // 256

    for (;;) {
        int u = grab();
        if (u >= NU_QMAT) break;
        const int dc = u & 31;
        const int b  = u >> 5;

        {
            const float4* s = reinterpret_cast<const float4*>(g_coef + (size_t)b * NN * RR);
            float4* dst = reinterpret_cast<float4*>(cfs);
#pragma unroll
            for (int i = 0; i < 16; ++i) dst[tid + i * 128] = s[tid + i * 128];
        }
        if (tid < 64) {
            float4 s = make_float4(0.f, 0.f, 0.f, 0.f);
#pragma unroll
            for (int sl = 0; sl < NCTC; ++sl) {
                float4 v = *reinterpret_cast<const float4*>(
                    g_ctcp + ((size_t)b * NCTC + sl) * 256 + tid * 4);
                s.x += v.x; s.y += v.y; s.z += v.z; s.w += v.w;
            }
            *reinterpret_cast<float4*>(&ctcs[tid * 4]) = s;
        }
        __syncthreads();

        const int d = dc * 128 + tid;
        u64 acc2[8];
#pragma unroll
        for (int q = 0; q < 8; ++q) acc2[q] = 0ull;

        const float* xb = x + (size_t)b * NN * DD + d;
#pragma unroll 1
        for (int n0 = 0; n0 < NN; n0 += 16) {
            float xv[16];
#pragma unroll
            for (int un = 0; un < 16; ++un) xv[un] = xb[(size_t)(n0 + un) * DD];
#pragma unroll
            for (int un = 0; un < 16; ++un)
                fma16_2(acc2, packf2(xv[un], xv[un]), &cfs[(n0 + un) * RR]);
        }
        float acc[16];
        unpack_acc(acc2, acc);

        float bs[16];
        load16(bold + ((size_t)b * DD + d) * RR, bs);
        float den[16];
        mat16(den, bs, ctcs);
#pragma unroll
        for (int r = 0; r < 16; ++r) bs[r] = bs[r] * acc[r] / (den[r] + EPSV);
        store16(g_bases + ((size_t)b * DD + d) * RR, bs);

        __syncthreads();
        float (*smb)[17] = reinterpret_cast<float (*)[17]>(cfs);
#pragma unroll
        for (int r = 0; r < 16; ++r) smb[tid][r] = bs[r];
        __syncthreads();
#pragma unroll
        for (int k = 0; k < 2; ++k) {
            int p2 = tid + k * 128;
            int r = p2 >> 4, s2 = p2 & 15;
            float s = 0.f;
#pragma unroll 8
            for (int i = 0; i < 128; ++i) s = fmaf(smb[i][r], smb[i][s2], s);
            g_btbp[((size_t)b * NBTB + dc) * 256 + p2] = s;
        }
        __syncthreads();
    }
}

// ---------------- out phase ----------------
__device__ void out_phase(float* __restrict__ out) {
    const int tid = threadIdx.x;
    float* cfs = smu;

    for (;;) {
        int u = grab();
        if (u >= NU_OUT) break;
        const int dc = u & 31;
        const int b  = u >> 5;

        {
            const float4* s = reinterpret_cast<const float4*>(g_coef + (size_t)b * NN * RR);
            float4* dst = reinterpret_cast<float4*>(cfs);
#pragma unroll
            for (int i = 0; i < 16; ++i) dst[tid + i * 128] = s[tid + i * 128];
        }
        __syncthreads();

        const int d = dc * 128 + tid;
        float bsv[16];
        load16(g_bases + ((size_t)b * DD + d) * RR, bsv);
        u64 bs2[8];
#pragma unroll
        for (int q = 0; q < 8; ++q) bs2[q] = packf2(bsv[2*q], bsv[2*q+1]);

        float* ob = out + (size_t)b * NN * DD + d;
#pragma unroll 4
        for (int n = 0; n < NN; ++n) {
            const ulonglong2* c2 = reinterpret_cast<const ulonglong2*>(&cfs[n * RR]);
            u64 o2a = 0ull, o2b = 0ull;
#pragma unroll
            for (int q = 0; q < 4; ++q) {
                ulonglong2 pq = c2[q];
                ffma2(o2a, bs2[2*q+0], pq.x);
                ffma2(o2b, bs2[2*q+1], pq.y);
            }
            float a0, a1, b0, b1;
            unpackf2(o2a, a0, a1);
            unpackf2(o2b, b0, b1);
            ob[(size_t)n * DD] = (a0 + a1) + (b0 + b1);
        }
        __syncthreads();
    }
}

// ---------------- state reset (replay safety) ----------------
__global__ void k_reset() {
    g_gen = 0u;
    g_arrive = 0u;
    g_work = 0u;
}

// ---------------- the one persistent kernel ----------------
__global__ void __launch_bounds__(TPB, 4) k_all(const float* __restrict__ x,
                                                const float* __restrict__ bases_in,
                                                float* __restrict__ out) {
    // belt-and-braces: base generation read at entry (stable until first barrier)
    unsigned gen = *((volatile unsigned*)&g_gen);

    pmat_phase(x, bases_in, true);          // P(X, bases0) + BtB(bases0)
    gen = grid_barrier(gen);

    coef_phase(true);                       // softmax init + coef update #1 (+ CtC)
    gen = grid_barrier(gen);

    for (int it = 0; it < 7; ++it) {
        qmat_phase(x, it == 0 ? bases_in : g_bases);  // bases update (+ BtB)
        gen = grid_barrier(gen);
        pmat_phase(x, g_bases, false);
        gen = grid_barrier(gen);
        coef_phase(false);                  // coef update (+ CtC)
        gen = grid_barrier(gen);
    }

    out_phase(out);
}

extern "C" void kernel_launch(void* const* d_in, const int* in_sizes, int n_in,
                              void* d_out, int out_size) {
    (void)in_sizes; (void)n_in; (void)out_size;
    const float* x     = (const float*)d_in[0];
    const float* bases = (const float*)d_in[1];
    float* out = (float*)d_out;

    k_reset<<<1, 1>>>();
    k_all<<<GRID, TPB>>>(x, bases, out);
}